// round 17
// baseline (speedup 1.0000x reference)
#include <cuda_runtime.h>
#include <cstdint>
#include <math.h>

// Problem constants (fixed: VOCAB=32, EMB=64, HID=1024, BATCH=2048, MAXLEN=100)
#define BATCH  2048
#define HID    1024
#define EMB    64
#define VOCAB  32
#define MAXLEN 100
#define SEQW   (MAXLEN+1)
#define PADTOK 0
#define EOSTOK 2

#define NCTA   256     // CTAs; each owns RPC rows for the whole generation
#define RPC    8       // rows per CTA
#define TPB    512     // threads; warp = 4 cols x 8 k-lanes; 16 warps
#define NPASS  16      // column passes: 16 * 64 cols = 1024
#define HS     1028    // padded k-stride for h/c tiles (bank-conflict-free)
#define XS     68      // padded k-stride for x tile

// R16 post-mortem: 1.73 FFMA-instr/cyc/SM vs structural max 2 (rt_SMSP=2) ->
// FFMA-ISSUE-BOUND, not memory-bound. This round: packed fma.rn.f32x2 over
// k-pairs. Both w and a float4 loads already hold (k,k+1) adjacent register
// pairs -> ZERO packing MOVs; FMA instruction count halves. acc becomes f32x2
// (even/odd-k partials), collapsed at reduce. 1 col/thread keeps acc at 64 regs.

struct Smem {
    float h0[2][RPC][HS];     // 65.8KB  layer-0 h, [buf][row][k]
    float h1[2][RPC][HS];     // 65.8KB
    float c0[RPC][HS];        // 32.9KB
    float c1[RPC][HS];        // 32.9KB
    float xs[RPC][XS];        // 2.2KB   emb[prev] gather, [row][k]
    float part[RPC][VOCAB];   // 1KB
    uint2 keys[MAXLEN];       // 800B
    int   prev[RPC];
    int   isend[RPC];
    int   len[RPC];
};                            // ~201.5KB dynamic shared

// ---------------- Threefry-2x32 (matches jax._src.prng) ----------------
__device__ __forceinline__ uint2 tf2x32(uint2 k, uint2 x) {
    uint32_t ks0 = k.x, ks1 = k.y, ks2 = k.x ^ k.y ^ 0x1BD11BDAu;
    uint32_t x0 = x.x + ks0, x1 = x.y + ks1;
#define TFR(r) { x0 += x1; x1 = __funnelshift_l(x1, x1, (r)); x1 ^= x0; }
    TFR(13) TFR(15) TFR(26) TFR(6)   x0 += ks1; x1 += ks2 + 1u;
    TFR(17) TFR(29) TFR(16) TFR(24)  x0 += ks2; x1 += ks0 + 2u;
    TFR(13) TFR(15) TFR(26) TFR(6)   x0 += ks0; x1 += ks1 + 3u;
    TFR(17) TFR(29) TFR(16) TFR(24)  x0 += ks1; x1 += ks2 + 4u;
    TFR(13) TFR(15) TFR(26) TFR(6)   x0 += ks2; x1 += ks0 + 5u;
#undef TFR
    return make_uint2(x0, x1);
}

// XLA expands logistic(x) as 0.5 + 0.5*tanh(0.5*x)
__device__ __forceinline__ float sigmoid_x(float x) { return 0.5f * tanhf(0.5f * x) + 0.5f; }

// Packed fp32x2 FMA (Blackwell FFMA2): d = a*b + d elementwise on 2 floats.
__device__ __forceinline__ void fma2(unsigned long long& d,
                                     unsigned long long a, unsigned long long b) {
    asm("fma.rn.f32x2 %0, %1, %2, %3;" : "=l"(d) : "l"(a), "l"(b), "l"(d));
}
__device__ __forceinline__ float2 unpack2(unsigned long long v) {
    float lo, hi;
    asm("mov.b64 {%0, %1}, %2;" : "=f"(lo), "=f"(hi) : "l"(v));
    return make_float2(lo, hi);
}

union F4U { float4 f4; unsigned long long u[2]; };

// Partial GEMM over this lane's k-slice (k = i*32 + kl*4 + {0..3}):
// acc[g][r] (f32x2: even/odd-k partials) += W[g*HID+col][k] * AsT[r][k].
// Both operands' (k,k+1) pairs are natural register pairs of float4 loads.
__device__ __forceinline__ void kslicep(unsigned long long (&acc)[4][RPC],
                                        const float* __restrict__ W,
                                        const float* __restrict__ AsT, int stride,
                                        int col, int K, int kl) {
    const float* wp0 = W + (size_t)(0 * HID + col) * K + kl * 4;
    const float* wp1 = W + (size_t)(1 * HID + col) * K + kl * 4;
    const float* wp2 = W + (size_t)(2 * HID + col) * K + kl * 4;
    const float* wp3 = W + (size_t)(3 * HID + col) * K + kl * 4;
    const int ni = K >> 5;
    for (int i = 0; i < ni; i++) {
        int koff = i << 5;
        F4U wv[4];
        wv[0].f4 = __ldg((const float4*)(wp0 + koff));
        wv[1].f4 = __ldg((const float4*)(wp1 + koff));
        wv[2].f4 = __ldg((const float4*)(wp2 + koff));
        wv[3].f4 = __ldg((const float4*)(wp3 + koff));
        int kbase = koff + (kl << 2);
        #pragma unroll
        for (int r = 0; r < RPC; r++) {
            F4U a;
            a.f4 = *(const float4*)(AsT + r * stride + kbase);
            #pragma unroll
            for (int g = 0; g < 4; g++) {
                fma2(acc[g][r], wv[g].u[0], a.u[0]);
                fma2(acc[g][r], wv[g].u[1], a.u[1]);
            }
        }
    }
}

// Collapse k-even/odd halves, reduce over the 8 k-lanes, add biases, apply
// the LSTM cell for row kl, store h,c.
__device__ __forceinline__ void reduce_cellp(unsigned long long (&acc)[4][RPC],
                                             const float* __restrict__ bih,
                                             const float* __restrict__ bhh,
                                             float* __restrict__ crow,   // &c[0][0]
                                             float* __restrict__ hrow,   // &h_new[0][0]
                                             int col, int kl) {
    float sac[4][RPC];
    #pragma unroll
    for (int g = 0; g < 4; g++)
        #pragma unroll
        for (int r = 0; r < RPC; r++) {
            float2 v = unpack2(acc[g][r]);
            float s = v.x + v.y;
            s += __shfl_xor_sync(0xffffffffu, s, 1);
            s += __shfl_xor_sync(0xffffffffu, s, 2);
            s += __shfl_xor_sync(0xffffffffu, s, 4);
            sac[g][r] = s;
        }
    float gi = 0.f, gf = 0.f, gg = 0.f, go = 0.f;
    #pragma unroll
    for (int r = 0; r < RPC; r++)
        if (kl == r) { gi = sac[0][r]; gf = sac[1][r]; gg = sac[2][r]; go = sac[3][r]; }
    gi += bih[col]         + bhh[col];
    gf += bih[HID + col]   + bhh[HID + col];
    gg += bih[2*HID + col] + bhh[2*HID + col];
    go += bih[3*HID + col] + bhh[3*HID + col];
    float cold = crow[kl * HS + col];
    float cn = sigmoid_x(gf) * cold + sigmoid_x(gi) * tanhf(gg);
    crow[kl * HS + col] = cn;
    hrow[kl * HS + col] = sigmoid_x(go) * tanhf(cn);
}

__global__ __launch_bounds__(TPB, 1)
void organ_persistent(const int* __restrict__ prevs, const float* __restrict__ emb,
                      const float* __restrict__ Wih0, const float* __restrict__ Whh0,
                      const float* __restrict__ bih0, const float* __restrict__ bhh0,
                      const float* __restrict__ Wih1, const float* __restrict__ Whh1,
                      const float* __restrict__ bih1, const float* __restrict__ bhh1,
                      const float* __restrict__ Wout, const float* __restrict__ bout,
                      float* __restrict__ out, int write_len) {
    extern __shared__ char smem_raw[];
    Smem& S = *reinterpret_cast<Smem*>(smem_raw);
    const int t = threadIdx.x;
    const int w = t >> 5;
    const int c = (t >> 3) & 3;
    const int kl = t & 7;
    const int rowBase = blockIdx.x * RPC;

    // ---- init shared state ----
    for (int i = t; i < RPC * HS; i += TPB) {
        (&S.h0[0][0][0])[i] = 0.f;
        (&S.h1[0][0][0])[i] = 0.f;
        (&S.c0[0][0])[i] = 0.f;
        (&S.c1[0][0])[i] = 0.f;
    }
    if (t < RPC) {
        int p = prevs[rowBase + t];
        S.prev[t]  = p & (VOCAB - 1);
        S.isend[t] = (p == EOSTOK) ? 1 : 0;
        S.len[t]   = 0;
        out[(size_t)(rowBase + t) * SEQW] = (float)p;
    }
    if (t < MAXLEN) {
        // jax.random.split, threefry_partitionable=True (foldlike):
        // keys[i] = threefry2x32(key(0,42), (hi=0, lo=i))
        S.keys[t] = tf2x32(make_uint2(0u, 42u), make_uint2(0u, (uint32_t)t));
    }
    __syncthreads();

    for (int s = 0; s < MAXLEN; s++) {
        const int cur = s & 1, nxt = cur ^ 1;

        // ---- gather x = emb[prev] into xs[r][k] ----
        {
            int k = t >> 3, r = t & 7;
            S.xs[r][k] = emb[S.prev[r] * EMB + k];
        }
        __syncthreads();

        // ---- layer 0: gates = h0 @ Whh0^T + x @ Wih0^T + b ----
        #pragma unroll 1
        for (int pass = 0; pass < NPASS; pass++) {
            int col = pass * 64 + w * 4 + c;
            unsigned long long acc[4][RPC];
            #pragma unroll
            for (int g = 0; g < 4; g++)
                #pragma unroll
                for (int r = 0; r < RPC; r++) acc[g][r] = 0ull;
            kslicep(acc, Whh0, &S.h0[cur][0][0], HS, col, HID, kl);
            kslicep(acc, Wih0, &S.xs[0][0],      XS, col, EMB, kl);
            reduce_cellp(acc, bih0, bhh0, &S.c0[0][0], &S.h0[nxt][0][0], col, kl);
        }
        __syncthreads();

        // ---- layer 1: gates = h0_new @ Wih1^T + h1 @ Whh1^T + b ----
        #pragma unroll 1
        for (int pass = 0; pass < NPASS; pass++) {
            int col = pass * 64 + w * 4 + c;
            unsigned long long acc[4][RPC];
            #pragma unroll
            for (int g = 0; g < 4; g++)
                #pragma unroll
                for (int r = 0; r < RPC; r++) acc[g][r] = 0ull;
            kslicep(acc, Wih1, &S.h0[nxt][0][0], HS, col, HID, kl);
            kslicep(acc, Whh1, &S.h1[cur][0][0], HS, col, HID, kl);
            reduce_cellp(acc, bih1, bhh1, &S.c1[0][0], &S.h1[nxt][0][0], col, kl);
        }
        __syncthreads();

        // ---- logits: part[r][v] = sum_k h1T[r][k] * Wout[v][k] ----
        {
            int v = t >> 4;            // 0..31
            int kb = t & 15;           // k-lane within group of 16
            const float* wv = Wout + (size_t)v * HID;
            const float* h1n = &S.h1[nxt][0][0];
            float p[RPC];
            #pragma unroll
            for (int r = 0; r < RPC; r++) p[r] = 0.f;
            for (int k = kb; k < HID; k += 16) {
                float wgt = __ldg(wv + k);
                #pragma unroll
                for (int r = 0; r < RPC; r++)
                    p[r] = fmaf(h1n[r * HS + k], wgt, p[r]);
            }
            #pragma unroll
            for (int off = 8; off >= 1; off >>= 1)
                #pragma unroll
                for (int r = 0; r < RPC; r++)
                    p[r] += __shfl_down_sync(0xffffffffu, p[r], off, 16);
            if (kb == 0)
                #pragma unroll
                for (int r = 0; r < RPC; r++) S.part[r][v] = p[r];
        }
        __syncthreads();

        // ---- jax.random.categorical + state update (warp r -> row r) ----
        if (t < RPC * 32) {
            int r = t >> 5, v = t & 31;
            int gr = rowBase + r;
            float logit = S.part[r][v] + bout[v];

            // random_bits (partitionable foldlike): counts (0, idx); out0^out1
            uint2 key = S.keys[s];
            uint32_t idx = (uint32_t)(gr * VOCAB + v);
            uint2 o = tf2x32(key, make_uint2(0u, idx));
            uint32_t bits = o.x ^ o.y;

            const float tiny = 1.17549435e-38f;
            float f = __uint_as_float((bits >> 9) | 0x3f800000u) - 1.0f;
            float u = fmaxf(f * (1.0f - tiny) + tiny, tiny);
            float gmb = -logf(-logf(u));
            float val = gmb + logit;

            int bi = v;   // first-index argmax (jnp.argmax semantics)
            #pragma unroll
            for (int off = 16; off > 0; off >>= 1) {
                float ov = __shfl_down_sync(0xffffffffu, val, off);
                int   oi = __shfl_down_sync(0xffffffffu, bi, off);
                if (ov > val || (ov == val && oi < bi)) { val = ov; bi = oi; }
            }
            if (v == 0) {
                int old_end = S.isend[r];
                int tok = old_end ? PADTOK : bi;
                if (!old_end) S.len[r] += 1;
                S.isend[r] = old_end | (tok == EOSTOK);
                S.prev[r] = tok;
                out[(size_t)gr * SEQW + s + 1] = (float)tok;
            }
        }
        __syncthreads();
    }

    if (write_len && t < RPC)
        out[(size_t)BATCH * SEQW + rowBase + t] = (float)(S.len[t] + 1);
}

// ---------------- launcher: resolve input roles by size signature -----------
extern "C" void kernel_launch(void* const* d_in, const int* in_sizes, int n_in,
                              void* d_out, int out_size) {
    int iprevs, iemb, iWih0, iWhh0, ibih0, ibhh0, iWih1, iWhh1, ibih1, ibhh1, iWout, ibout;
    if (n_in >= 12 && in_sizes[0] == 2048 && in_sizes[1] == 2048) {
        iprevs=0; iemb=1; iWih0=2; iWhh0=3; ibih0=4; ibhh0=5;
        iWih1=6; iWhh1=7; ibih1=8; ibhh1=9; iWout=10; ibout=11;
    } else if (n_in >= 13 && in_sizes[0] == 4194304) {
        iWhh0=0; iWhh1=1; iWih0=2; iWih1=3; iWout=4; ibhh0=5; ibhh1=6;
        ibih0=7; ibih1=8; ibout=9; iemb=10; iprevs=12;
        if (in_sizes[11] == 2048 && in_sizes[12] != 2048) iprevs = 11;
    } else if (n_in >= 13 && in_sizes[0] == 4096) {
        ibhh0=0; ibhh1=1; ibih0=2; ibih1=3; ibout=4; iemb=5; iprevs=7;
        iWhh0=8; iWhh1=9; iWih0=10; iWih1=11; iWout=12;
        if (in_sizes[6] == 2048 && in_sizes[7] != 2048) {
            iprevs=6; iWhh0=7; iWhh1=8; iWih0=9; iWih1=10; iWout=11;
        }
    } else {
        iprevs=0; iemb=1; iWih0=2; iWhh0=3; ibih0=4; ibhh0=5;
        iWih1=6; iWhh1=7; ibih1=8; ibhh1=9; iWout=10; ibout=11;
    }

    const int*   prevs = (const int*)d_in[iprevs];
    const float* emb   = (const float*)d_in[iemb];
    const float* Wih0  = (const float*)d_in[iWih0];
    const float* Whh0  = (const float*)d_in[iWhh0];
    const float* bih0  = (const float*)d_in[ibih0];
    const float* bhh0  = (const float*)d_in[ibhh0];
    const float* Wih1  = (const float*)d_in[iWih1];
    const float* Whh1  = (const float*)d_in[iWhh1];
    const float* bih1  = (const float*)d_in[ibih1];
    const float* bhh1  = (const float*)d_in[ibhh1];
    const float* Wout  = (const float*)d_in[iWout];
    const float* bout  = (const float*)d_in[ibout];
    float* out = (float*)d_out;   // __output__ dtype: float32 (R14-verified)

    cudaFuncSetAttribute(organ_persistent,
                         cudaFuncAttributeMaxDynamicSharedMemorySize,
                         (int)sizeof(Smem));
    int write_len = (out_size >= BATCH * SEQW + BATCH) ? 1 : 0;
    organ_persistent<<<NCTA, TPB, sizeof(Smem)>>>(
        prevs, emb, Wih0, Whh0, bih0, bhh0, Wih1, Whh1, bih1, bhh1,
        Wout, bout, out, write_len);
}